// round 1
// baseline (speedup 1.0000x reference)
#include <cuda_runtime.h>

#define NN 500000
#define EE 8000000
#define GG 8192
#define STR 12
#define BN_EPS 1e-5f

// ---------------- scratch (device globals; no allocations) ----------------
__device__ __align__(16) float d_bufA[(size_t)NN * STR];
__device__ __align__(16) float d_bufB[(size_t)NN * STR];
__device__ __align__(16) float d_agg [(size_t)NN * STR];
__device__ float d_deg[NN];
__device__ float d_stats[3 * 32];   // per layer: sum[0..16), sumsq[16..32)
__device__ float d_aff  [3 * 32];   // per layer: a[0..16), c[16..32)
__device__ float d_psum[GG * 10];
__device__ float d_cnt [GG];

// ---------------- vector global reductions (sm_90+) ----------------
__device__ __forceinline__ void red_add_v4(float* p, float a, float b, float c, float d) {
    asm volatile("red.global.add.v4.f32 [%0], {%1,%2,%3,%4};"
                 :: "l"(p), "f"(a), "f"(b), "f"(c), "f"(d) : "memory");
}
__device__ __forceinline__ void red_add_v2(float* p, float a, float b) {
    asm volatile("red.global.add.v2.f32 [%0], {%1,%2};"
                 :: "l"(p), "f"(a), "f"(b) : "memory");
}

// ---------------- zero scratch ----------------
__global__ void zero_kernel() {
    size_t i = (size_t)blockIdx.x * blockDim.x + threadIdx.x;
    size_t stride = (size_t)gridDim.x * blockDim.x;
    float4 z4 = make_float4(0.f, 0.f, 0.f, 0.f);
    float4* a4 = (float4*)d_agg;
    size_t n4 = (size_t)NN * STR / 4;
    for (size_t k = i; k < n4; k += stride) a4[k] = z4;
    for (size_t k = i; k < NN; k += stride) d_deg[k] = 0.f;
    for (size_t k = i; k < (size_t)GG * 10; k += stride) d_psum[k] = 0.f;
    for (size_t k = i; k < GG; k += stride) d_cnt[k] = 0.f;
    if (i < 3 * 32) d_stats[i] = 0.f;
}

// ---------------- pack x (N x 5) into padded bufA ----------------
__global__ void pack_kernel(const float* __restrict__ x) {
    int n = blockIdx.x * blockDim.x + threadIdx.x;
    if (n >= NN) return;
    #pragma unroll
    for (int f = 0; f < 5; f++) d_bufA[(size_t)n * STR + f] = x[(size_t)n * 5 + f];
}

// ---------------- edge scatter: agg[dst] += h[src] ----------------
template<int F, bool DEG, bool SRC_A>
__global__ __launch_bounds__(256) void edge_kernel(const int* __restrict__ ei) {
    int e = blockIdx.x * blockDim.x + threadIdx.x;
    if (e >= EE) return;
    int s = __ldg(ei + e);
    int d = __ldg(ei + EE + e);
    const float* hin = SRC_A ? d_bufA : d_bufB;
    const float4* hp = reinterpret_cast<const float4*>(hin + (size_t)s * STR);
    float* ap = d_agg + (size_t)d * STR;
    float4 v0 = __ldg(hp);
    if (F == 5) {
        float v4 = __ldg(hin + (size_t)s * STR + 4);
        red_add_v4(ap, v0.x, v0.y, v0.z, v0.w);
        atomicAdd(ap + 4, v4);
    } else {
        float4 v1 = __ldg(hp + 1);
        float2 v2 = __ldg(reinterpret_cast<const float2*>(hin + (size_t)s * STR + 8));
        red_add_v4(ap,     v0.x, v0.y, v0.z, v0.w);
        red_add_v4(ap + 4, v1.x, v1.y, v1.z, v1.w);
        red_add_v2(ap + 8, v2.x, v2.y);
    }
    if (DEG) atomicAdd(&d_deg[d], 1.0f);
}

// ---------------- node MLP + relu + BN-stats (BN affine of previous layer folded in) ----------------
template<int FIN, int FMID, int FOUT, bool AFF, bool IN_A>
__global__ __launch_bounds__(256) void node_kernel(
    const float* __restrict__ w1, const float* __restrict__ b1,
    const float* __restrict__ w2, const float* __restrict__ b2,
    int layer)
{
    __shared__ float sw1[FIN * FMID], sb1[FMID], sw2[FMID * FOUT], sb2[FOUT];
    __shared__ float saff[32];
    __shared__ float redsh[8][2 * FOUT];
    int tid = threadIdx.x;
    if (tid < FIN * FMID) sw1[tid] = w1[tid];
    if (tid < FMID)       sb1[tid] = b1[tid];
    if (tid < FMID * FOUT) sw2[tid] = w2[tid];
    if (tid < FOUT)       sb2[tid] = b2[tid];
    if (AFF && tid < 32)  saff[tid] = d_aff[(layer - 1) * 32 + tid];
    __syncthreads();

    int n = blockIdx.x * 256 + tid;
    bool valid = n < NN;
    float r[FOUT];
    #pragma unroll
    for (int j = 0; j < FOUT; j++) r[j] = 0.f;

    if (valid) {
        const float* hin  = IN_A ? d_bufA : d_bufB;
        float*       hout = IN_A ? d_bufB : d_bufA;
        const float* hp = hin + (size_t)n * STR;
        float*       ap = d_agg + (size_t)n * STR;
        float t[FIN];
        float degc = AFF ? (1.0f + d_deg[n]) : 0.f;
        #pragma unroll
        for (int f = 0; f < FIN; f++) {
            float v = hp[f] + ap[f];
            t[f] = AFF ? (saff[f] * v + saff[16 + f] * degc) : v;
        }
        // zero agg row for the next layer's scatter
        float4 z = make_float4(0.f, 0.f, 0.f, 0.f);
        float4* az = (float4*)ap;
        az[0] = z; az[1] = z; az[2] = z;

        float u[FMID];
        #pragma unroll
        for (int j = 0; j < FMID; j++) {
            float a = sb1[j];
            #pragma unroll
            for (int i = 0; i < FIN; i++) a += t[i] * sw1[i * FMID + j];
            u[j] = fmaxf(a, 0.f);
        }
        #pragma unroll
        for (int j = 0; j < FOUT; j++) {
            float a = sb2[j];
            #pragma unroll
            for (int i = 0; i < FMID; i++) a += u[i] * sw2[i * FOUT + j];
            r[j] = fmaxf(a, 0.f);
            hout[(size_t)n * STR + j] = r[j];
        }
    }

    // BN statistics: 2-level reduction, then a few global atomics per block
    int lane = tid & 31, warp = tid >> 5;
    #pragma unroll
    for (int f = 0; f < FOUT; f++) {
        float s = r[f], q = r[f] * r[f];
        #pragma unroll
        for (int d2 = 16; d2; d2 >>= 1) {
            s += __shfl_down_sync(0xffffffffu, s, d2);
            q += __shfl_down_sync(0xffffffffu, q, d2);
        }
        if (lane == 0) { redsh[warp][f] = s; redsh[warp][FOUT + f] = q; }
    }
    __syncthreads();
    if (tid < 2 * FOUT) {
        float acc = 0.f;
        #pragma unroll
        for (int w = 0; w < 8; w++) acc += redsh[w][tid];
        float* st = d_stats + layer * 32;
        int idx = (tid < FOUT) ? tid : (16 + tid - FOUT);
        atomicAdd(&st[idx], acc);
    }
}

// ---------------- per-layer BN parameters -> affine (a, c) ----------------
__global__ void finalize_kernel(const float* __restrict__ g, const float* __restrict__ be,
                                int layer, int F) {
    int f = threadIdx.x;
    if (f < F) {
        const float* st = d_stats + layer * 32;
        float mu  = st[f] * (1.0f / NN);
        float var = st[16 + f] * (1.0f / NN) - mu * mu;
        float a = g[f] * rsqrtf(var + BN_EPS);
        d_aff[layer * 32 + f]      = a;
        d_aff[layer * 32 + 16 + f] = be[f] - mu * a;
    }
}

// ---------------- pooling: warp-segmented sums over sorted batch ----------------
__global__ __launch_bounds__(256) void pool_kernel(const int* __restrict__ batch) {
    int n = blockIdx.x * 256 + threadIdx.x;
    if (n >= NN) return;   // NN % 32 == 0: warps are uniformly valid
    int lane = threadIdx.x & 31;
    int b = __ldg(batch + n);
    const float* hp = d_bufB + (size_t)n * STR;
    float4 a = *(const float4*)hp;
    float4 c = *(const float4*)(hp + 4);
    float2 e2 = *(const float2*)(hp + 8);
    float v[10] = {a.x, a.y, a.z, a.w, c.x, c.y, c.z, c.w, e2.x, e2.y};
    float cnt = 1.f;
    unsigned m = 0xffffffffu;
    #pragma unroll
    for (int d2 = 1; d2 < 32; d2 <<= 1) {
        int nb = __shfl_down_sync(m, b, d2);
        float ncnt = __shfl_down_sync(m, cnt, d2);
        float nv[10];
        #pragma unroll
        for (int f = 0; f < 10; f++) nv[f] = __shfl_down_sync(m, v[f], d2);
        if (lane + d2 < 32 && nb == b) {
            cnt += ncnt;
            #pragma unroll
            for (int f = 0; f < 10; f++) v[f] += nv[f];
        }
    }
    int pb = __shfl_up_sync(m, b, 1);
    if (lane == 0 || pb != b) {
        #pragma unroll
        for (int f = 0; f < 10; f++) atomicAdd(&d_psum[(size_t)b * 10 + f], v[f]);
        atomicAdd(&d_cnt[b], cnt);
    }
}

// ---------------- final MLP: one warp per graph ----------------
__global__ __launch_bounds__(256) void fc_kernel(
    const float* __restrict__ gx,
    const float* __restrict__ fw1, const float* __restrict__ fb1,
    const float* __restrict__ fw2, const float* __restrict__ fb2,
    const float* __restrict__ fw3, const float* __restrict__ fb3,
    float* __restrict__ out)
{
    __shared__ float s1[20 * 128];
    __shared__ float s2[128 * 64];
    __shared__ float s3[64];
    __shared__ float sb1[128];
    __shared__ float sb2[64];
    __shared__ float sh[8][128];
    __shared__ float sz[8][20];
    int tid = threadIdx.x;
    for (int k = tid; k < 2560; k += 256) s1[k] = fw1[k];
    for (int k = tid; k < 8192; k += 256) s2[k] = fw2[k];
    if (tid < 64)  s3[tid]  = fw3[tid];
    if (tid < 128) sb1[tid] = fb1[tid];
    if (tid < 64)  sb2[tid] = fb2[tid];

    int warp = tid >> 5, lane = tid & 31;
    int g = blockIdx.x * 8 + warp;
    if (lane < 10) {
        float c = d_cnt[g];
        const float* aff = d_aff + 2 * 32;
        float p = (c > 0.f) ? aff[lane] * (d_psum[(size_t)g * 10 + lane] / c) + aff[16 + lane] : 0.f;
        sz[warp][lane] = p;
        sz[warp][10 + lane] = gx[(size_t)g * 10 + lane];
    }
    __syncthreads();

    float h[4];
    #pragma unroll
    for (int k = 0; k < 4; k++) {
        int j = lane + 32 * k;
        float acc = sb1[j];
        #pragma unroll
        for (int i = 0; i < 20; i++) acc += sz[warp][i] * s1[i * 128 + j];
        h[k] = fmaxf(acc, 0.f);
        sh[warp][j] = h[k];
    }
    __syncwarp();
    float o0, o1;
    {
        int j = lane;
        float acc = sb2[j];
        #pragma unroll 8
        for (int i = 0; i < 128; i++) acc += sh[warp][i] * s2[i * 64 + j];
        o0 = fmaxf(acc, 0.f);
        j = lane + 32;
        acc = sb2[j];
        #pragma unroll 8
        for (int i = 0; i < 128; i++) acc += sh[warp][i] * s2[i * 64 + j];
        o1 = fmaxf(acc, 0.f);
    }
    float part = o0 * s3[lane] + o1 * s3[lane + 32];
    #pragma unroll
    for (int d2 = 16; d2; d2 >>= 1) part += __shfl_down_sync(0xffffffffu, part, d2);
    if (lane == 0) out[g] = part + __ldg(fb3);
}

// ---------------- launch ----------------
extern "C" void kernel_launch(void* const* d_in, const int* in_sizes, int n_in,
                              void* d_out, int out_size) {
    const float* x     = (const float*)d_in[0];
    const int*   ei    = (const int*)  d_in[1];
    const int*   batch = (const int*)  d_in[2];
    const float* gx    = (const float*)d_in[3];
    const float* w11 = (const float*)d_in[4],  *b11 = (const float*)d_in[5];
    const float* w12 = (const float*)d_in[6],  *b12 = (const float*)d_in[7];
    const float* w21 = (const float*)d_in[8],  *b21 = (const float*)d_in[9];
    const float* w22 = (const float*)d_in[10], *b22 = (const float*)d_in[11];
    const float* w31 = (const float*)d_in[12], *b31 = (const float*)d_in[13];
    const float* w32 = (const float*)d_in[14], *b32 = (const float*)d_in[15];
    const float* g1  = (const float*)d_in[16], *be1 = (const float*)d_in[17];
    const float* g2  = (const float*)d_in[18], *be2 = (const float*)d_in[19];
    const float* g3  = (const float*)d_in[20], *be3 = (const float*)d_in[21];
    const float* fw1 = (const float*)d_in[22], *fb1 = (const float*)d_in[23];
    const float* fw2 = (const float*)d_in[24], *fb2 = (const float*)d_in[25];
    const float* fw3 = (const float*)d_in[26], *fb3 = (const float*)d_in[27];
    float* out = (float*)d_out;

    const int NB_N = (NN + 255) / 256;
    const int NB_E = (EE + 255) / 256;

    zero_kernel<<<3072, 256>>>();
    pack_kernel<<<NB_N, 256>>>(x);

    // layer 1 (5 -> 5 -> 5), no input affine, accumulate deg
    edge_kernel<5, true, true><<<NB_E, 256>>>(ei);
    node_kernel<5, 5, 5, false, true><<<NB_N, 256>>>(w11, b11, w12, b12, 0);
    finalize_kernel<<<1, 32>>>(g1, be1, 0, 5);

    // layer 2 (5 -> 10 -> 10), BN(l1) folded via affine + deg
    edge_kernel<5, false, false><<<NB_E, 256>>>(ei);
    node_kernel<5, 10, 10, true, false><<<NB_N, 256>>>(w21, b21, w22, b22, 1);
    finalize_kernel<<<1, 32>>>(g2, be2, 1, 10);

    // layer 3 (10 -> 10 -> 10), BN(l2) folded
    edge_kernel<10, false, true><<<NB_E, 256>>>(ei);
    node_kernel<10, 10, 10, true, true><<<NB_N, 256>>>(w31, b31, w32, b32, 2);
    finalize_kernel<<<1, 32>>>(g3, be3, 2, 10);

    // pool (BN(l3) applied at pooled level inside fc) + final MLP
    pool_kernel<<<NB_N, 256>>>(batch);
    fc_kernel<<<GG / 8, 256>>>(gx, fw1, fb1, fw2, fb2, fw3, fb3, out);
}

// round 2
// speedup vs baseline: 1.0825x; 1.0825x over previous
#include <cuda_runtime.h>

#define NN 500000
#define EE 8000000
#define GG 8192
#define BN_EPS 1e-5f
#define NBS 489          // ceil(NN/1024) scan blocks
#define EPT 16           // edges per thread in gather
#define NTH (EE / EPT)   // 500000 gather threads

// ---------------- scratch (device globals; no allocations) ----------------
__device__ __align__(16) float d_h5a[(size_t)NN * 8];
__device__ __align__(16) float d_h5b[(size_t)NN * 8];
__device__ __align__(16) float d_h10[(size_t)NN * 12];
__device__ __align__(16) float d_agg[(size_t)NN * 12];
__device__ __align__(16) int2  d_edges[EE];
__device__ int   d_hist[NN];
__device__ int   d_rowptr[NN + 1];
__device__ int   d_pos[NN];
__device__ int   d_bsum[512];
__device__ int   d_bsumx[512];
__device__ float d_stats[3 * 32];   // per layer: sum[0..16), sumsq[16..32)
__device__ float d_aff  [3 * 32];   // per layer: a[0..16), c[16..32)
__device__ float d_psum[GG * 10];
__device__ float d_cnt [GG];

// ---------------- vector global reductions (sm_90+) ----------------
__device__ __forceinline__ void red_add_v4(float* p, float a, float b, float c, float d) {
    asm volatile("red.global.add.v4.f32 [%0], {%1,%2,%3,%4};"
                 :: "l"(p), "f"(a), "f"(b), "f"(c), "f"(d) : "memory");
}
__device__ __forceinline__ void red_add_v2(float* p, float a, float b) {
    asm volatile("red.global.add.v2.f32 [%0], {%1,%2};"
                 :: "l"(p), "f"(a), "f"(b) : "memory");
}

// ---------------- zero scratch ----------------
__global__ void zero_kernel() {
    size_t i = (size_t)blockIdx.x * blockDim.x + threadIdx.x;
    size_t stride = (size_t)gridDim.x * blockDim.x;
    float4 z4 = make_float4(0.f, 0.f, 0.f, 0.f);
    float4* a4 = (float4*)d_agg;
    size_t n4 = (size_t)NN * 12 / 4;
    for (size_t k = i; k < n4; k += stride) a4[k] = z4;
    for (size_t k = i; k < NN; k += stride) d_hist[k] = 0;
    for (size_t k = i; k < (size_t)GG * 10; k += stride) d_psum[k] = 0.f;
    for (size_t k = i; k < GG; k += stride) d_cnt[k] = 0.f;
    if (i < 3 * 32) d_stats[i] = 0.f;
}

// ---------------- pack x (N x 5) into 32B rows ----------------
__global__ void pack_kernel(const float* __restrict__ x) {
    int n = blockIdx.x * blockDim.x + threadIdx.x;
    if (n >= NN) return;
    #pragma unroll
    for (int f = 0; f < 5; f++) d_h5a[(size_t)n * 8 + f] = x[(size_t)n * 5 + f];
}

// ---------------- counting sort: histogram over dst ----------------
__global__ __launch_bounds__(256) void hist_kernel(const int* __restrict__ ei) {
    int e = blockIdx.x * blockDim.x + threadIdx.x;
    if (e < EE) atomicAdd(&d_hist[__ldg(ei + EE + e)], 1);
}

// ---------------- scan stage 1: per-block exclusive scan (1024 elems/block) --
__global__ __launch_bounds__(256) void scan1_kernel() {
    __shared__ int wsum[8];
    int tid = threadIdx.x, b = blockIdx.x;
    int lane = tid & 31, warp = tid >> 5;
    int base = b * 1024 + tid * 4;
    int v[4];
    #pragma unroll
    for (int j = 0; j < 4; j++) {
        int idx = base + j;
        v[j] = (idx < NN) ? d_hist[idx] : 0;
    }
    int tsum = v[0] + v[1] + v[2] + v[3];
    int inc = tsum;
    #pragma unroll
    for (int d = 1; d < 32; d <<= 1) {
        int t = __shfl_up_sync(0xffffffffu, inc, d);
        if (lane >= d) inc += t;
    }
    if (lane == 31) wsum[warp] = inc;
    __syncthreads();
    int woff = 0;
    for (int w = 0; w < warp; w++) woff += wsum[w];
    int run = woff + inc - tsum;   // exclusive prefix of this thread
    #pragma unroll
    for (int j = 0; j < 4; j++) {
        int idx = base + j;
        if (idx < NN) d_rowptr[idx] = run;
        run += v[j];
    }
    if (tid == 255) d_bsum[b] = woff + inc;
}

// ---------------- scan stage 2: scan the 489 block sums ----------------
__global__ void scan2_kernel() {
    __shared__ int s[512];
    int tid = threadIdx.x;
    int v = (tid < NBS) ? d_bsum[tid] : 0;
    s[tid] = v;
    __syncthreads();
    for (int d = 1; d < 512; d <<= 1) {
        int t = (tid >= d) ? s[tid - d] : 0;
        __syncthreads();
        s[tid] += t;
        __syncthreads();
    }
    if (tid < NBS) d_bsumx[tid] = s[tid] - v;
}

// ---------------- scan stage 3: add offsets, init pos, cap rowptr ----------
__global__ __launch_bounds__(256) void scan3_kernel() {
    int i = blockIdx.x * 256 + threadIdx.x;
    if (i < NN) {
        int r = d_rowptr[i] + d_bsumx[i >> 10];
        d_rowptr[i] = r;
        d_pos[i] = r;
    }
    if (i == 0) d_rowptr[NN] = EE;
}

// ---------------- scatter edges into dst-sorted order ----------------
__global__ __launch_bounds__(256) void scatter_kernel(const int* __restrict__ ei) {
    int e = blockIdx.x * blockDim.x + threadIdx.x;
    if (e >= EE) return;
    int s = __ldg(ei + e);
    int d = __ldg(ei + EE + e);
    int slot = atomicAdd(&d_pos[d], 1);
    d_edges[slot] = make_int2(s, d);
}

// ---------------- aggregation over sorted edges: register-segmented ----------
// SRC: 0 = d_h5a (str 8), 1 = d_h5b (str 8), 2 = d_h10 (str 12)
template<int F, int SRC>
__global__ __launch_bounds__(256) void gather_kernel() {
    int t = blockIdx.x * 256 + threadIdx.x;
    if (t >= NTH) return;
    const int4* ep = reinterpret_cast<const int4*>(d_edges) + (size_t)t * (EPT / 2);
    int4 E[EPT / 2];
    #pragma unroll
    for (int k = 0; k < EPT / 2; k++) E[k] = __ldg(ep + k);

    const float* hin = (SRC == 0) ? d_h5a : (SRC == 1) ? d_h5b : d_h10;
    const int hstr = (F == 5) ? 8 : 12;

    float acc[F];
    int cur = -1;
    #pragma unroll
    for (int j = 0; j < EPT; j++) {
        int s = (j & 1) ? ((j >> 1) < EPT/2 ? E[j >> 1].z : 0) : E[j >> 1].x;
        int d = (j & 1) ? E[j >> 1].w : E[j >> 1].y;
        if (j == 0) {
            cur = d;
            #pragma unroll
            for (int f = 0; f < F; f++) acc[f] = 0.f;
        } else if (d != cur) {
            float* ap = d_agg + (size_t)cur * 12;
            if (F == 5) { red_add_v4(ap, acc[0], acc[1], acc[2], acc[3]); atomicAdd(ap + 4, acc[4]); }
            else { red_add_v4(ap, acc[0], acc[1], acc[2], acc[3]);
                   red_add_v4(ap + 4, acc[4], acc[5], acc[6], acc[7]);
                   red_add_v2(ap + 8, acc[8], acc[9]); }
            #pragma unroll
            for (int f = 0; f < F; f++) acc[f] = 0.f;
            cur = d;
        }
        const float* hp = hin + (size_t)s * hstr;
        float4 a = __ldg(reinterpret_cast<const float4*>(hp));
        acc[0] += a.x; acc[1] += a.y; acc[2] += a.z; acc[3] += a.w;
        if (F == 5) {
            acc[4] += __ldg(hp + 4);
        } else {
            float4 b = __ldg(reinterpret_cast<const float4*>(hp) + 1);
            float2 c = __ldg(reinterpret_cast<const float2*>(hp + 8));
            acc[4] += b.x; acc[5] += b.y; acc[6] += b.z; acc[7] += b.w;
            acc[8] += c.x; acc[9] += c.y;
        }
    }
    float* ap = d_agg + (size_t)cur * 12;
    if (F == 5) { red_add_v4(ap, acc[0], acc[1], acc[2], acc[3]); atomicAdd(ap + 4, acc[4]); }
    else { red_add_v4(ap, acc[0], acc[1], acc[2], acc[3]);
           red_add_v4(ap + 4, acc[4], acc[5], acc[6], acc[7]);
           red_add_v2(ap + 8, acc[8], acc[9]); }
}

// ---------------- node MLP + relu + BN-stats (+ fused pool on last layer) ----
template<int FIN, int FMID, int FOUT, int LAYER>
__global__ __launch_bounds__(256) void node_kernel(
    const float* __restrict__ w1, const float* __restrict__ b1,
    const float* __restrict__ w2, const float* __restrict__ b2,
    const int* __restrict__ batch)
{
    constexpr bool AFF  = (LAYER > 0);
    constexpr bool LAST = (LAYER == 2);
    __shared__ float sw1[FIN * FMID], sb1[FMID], sw2[FMID * FOUT], sb2[FOUT];
    __shared__ float saff[32];
    __shared__ float redsh[8][2 * FOUT];
    int tid = threadIdx.x;
    if (tid < FIN * FMID)  sw1[tid] = w1[tid];
    if (tid < FMID)        sb1[tid] = b1[tid];
    if (tid < FMID * FOUT) sw2[tid] = w2[tid];
    if (tid < FOUT)        sb2[tid] = b2[tid];
    if (AFF && tid < 32)   saff[tid] = d_aff[(LAYER - 1) * 32 + tid];
    __syncthreads();

    int n = blockIdx.x * 256 + tid;
    bool valid = n < NN;
    float r[FOUT];
    #pragma unroll
    for (int j = 0; j < FOUT; j++) r[j] = 0.f;

    if (valid) {
        const float* hp = (LAYER == 0) ? &d_h5a[(size_t)n * 8]
                        : (LAYER == 1) ? &d_h5b[(size_t)n * 8]
                                       : &d_h10[(size_t)n * 12];
        float* ap = d_agg + (size_t)n * 12;
        float t[FIN];
        float degc = 0.f;
        if (AFF) degc = 1.0f + (float)(__ldg(d_rowptr + n + 1) - __ldg(d_rowptr + n));
        #pragma unroll
        for (int f = 0; f < FIN; f++) {
            float v = hp[f] + ap[f];
            t[f] = AFF ? (saff[f] * v + saff[16 + f] * degc) : v;
        }
        if (!LAST) {   // re-zero agg row for the next layer's scatter
            float4 z = make_float4(0.f, 0.f, 0.f, 0.f);
            float4* az = (float4*)ap;
            az[0] = z; az[1] = z; az[2] = z;
        }
        float u[FMID];
        #pragma unroll
        for (int j = 0; j < FMID; j++) {
            float a = sb1[j];
            #pragma unroll
            for (int i = 0; i < FIN; i++) a += t[i] * sw1[i * FMID + j];
            u[j] = fmaxf(a, 0.f);
        }
        #pragma unroll
        for (int j = 0; j < FOUT; j++) {
            float a = sb2[j];
            #pragma unroll
            for (int i = 0; i < FMID; i++) a += u[i] * sw2[i * FOUT + j];
            r[j] = fmaxf(a, 0.f);
        }
        if (!LAST) {
            float* ho = (LAYER == 0) ? &d_h5b[(size_t)n * 8] : &d_h10[(size_t)n * 12];
            #pragma unroll
            for (int j = 0; j < FOUT; j++) ho[j] = r[j];
        }
    }

    // BN statistics: warp reduce -> shared -> few global atomics per block
    int lane = tid & 31, warp = tid >> 5;
    #pragma unroll
    for (int f = 0; f < FOUT; f++) {
        float s = r[f], q = r[f] * r[f];
        #pragma unroll
        for (int d2 = 16; d2; d2 >>= 1) {
            s += __shfl_down_sync(0xffffffffu, s, d2);
            q += __shfl_down_sync(0xffffffffu, q, d2);
        }
        if (lane == 0) { redsh[warp][f] = s; redsh[warp][FOUT + f] = q; }
    }
    __syncthreads();
    if (tid < 2 * FOUT) {
        float acc = 0.f;
        #pragma unroll
        for (int w = 0; w < 8; w++) acc += redsh[w][tid];
        float* st = d_stats + LAYER * 32;
        int idx = (tid < FOUT) ? tid : (16 + tid - FOUT);
        atomicAdd(&st[idx], acc);
    }

    // fused pooling on the last layer (batch sorted; NN % 32 == 0)
    if (LAST) {
        if (valid) {   // whole warp uniformly valid
            int b = __ldg(batch + n);
            float v[11];
            #pragma unroll
            for (int f = 0; f < 10; f++) v[f] = r[f];
            v[10] = 1.f;
            unsigned m = 0xffffffffu;
            #pragma unroll
            for (int d2 = 1; d2 < 32; d2 <<= 1) {
                int nb = __shfl_down_sync(m, b, d2);
                float nv[11];
                #pragma unroll
                for (int f = 0; f < 11; f++) nv[f] = __shfl_down_sync(m, v[f], d2);
                if (lane + d2 < 32 && nb == b) {
                    #pragma unroll
                    for (int f = 0; f < 11; f++) v[f] += nv[f];
                }
            }
            int pb = __shfl_up_sync(m, b, 1);
            if (lane == 0 || pb != b) {
                #pragma unroll
                for (int f = 0; f < 10; f++) atomicAdd(&d_psum[(size_t)b * 10 + f], v[f]);
                atomicAdd(&d_cnt[b], v[10]);
            }
        }
    }
}

// ---------------- per-layer BN parameters -> affine (a, c) ----------------
__global__ void finalize_kernel(const float* __restrict__ g, const float* __restrict__ be,
                                int layer, int F) {
    int f = threadIdx.x;
    if (f < F) {
        const float* st = d_stats + layer * 32;
        float mu  = st[f] * (1.0f / NN);
        float var = st[16 + f] * (1.0f / NN) - mu * mu;
        float a = g[f] * rsqrtf(var + BN_EPS);
        d_aff[layer * 32 + f]      = a;
        d_aff[layer * 32 + 16 + f] = be[f] - mu * a;
    }
}

// ---------------- final MLP: one warp per graph ----------------
__global__ __launch_bounds__(256) void fc_kernel(
    const float* __restrict__ gx,
    const float* __restrict__ fw1, const float* __restrict__ fb1,
    const float* __restrict__ fw2, const float* __restrict__ fb2,
    const float* __restrict__ fw3, const float* __restrict__ fb3,
    float* __restrict__ out)
{
    __shared__ float s1[20 * 128];
    __shared__ float s2[128 * 64];
    __shared__ float s3[64];
    __shared__ float sb1[128];
    __shared__ float sb2[64];
    __shared__ float sh[8][128];
    __shared__ float sz[8][20];
    int tid = threadIdx.x;
    for (int k = tid; k < 2560; k += 256) s1[k] = fw1[k];
    for (int k = tid; k < 8192; k += 256) s2[k] = fw2[k];
    if (tid < 64)  s3[tid]  = fw3[tid];
    if (tid < 128) sb1[tid] = fb1[tid];
    if (tid < 64)  sb2[tid] = fb2[tid];

    int warp = tid >> 5, lane = tid & 31;
    int g = blockIdx.x * 8 + warp;
    if (lane < 10) {
        float c = d_cnt[g];
        const float* aff = d_aff + 2 * 32;
        float p = (c > 0.f) ? aff[lane] * (d_psum[(size_t)g * 10 + lane] / c) + aff[16 + lane] : 0.f;
        sz[warp][lane] = p;
        sz[warp][10 + lane] = gx[(size_t)g * 10 + lane];
    }
    __syncthreads();

    float h[4];
    #pragma unroll
    for (int k = 0; k < 4; k++) {
        int j = lane + 32 * k;
        float acc = sb1[j];
        #pragma unroll
        for (int i = 0; i < 20; i++) acc += sz[warp][i] * s1[i * 128 + j];
        h[k] = fmaxf(acc, 0.f);
        sh[warp][j] = h[k];
    }
    __syncwarp();
    float o0, o1;
    {
        int j = lane;
        float acc = sb2[j];
        #pragma unroll 8
        for (int i = 0; i < 128; i++) acc += sh[warp][i] * s2[i * 64 + j];
        o0 = fmaxf(acc, 0.f);
        j = lane + 32;
        acc = sb2[j];
        #pragma unroll 8
        for (int i = 0; i < 128; i++) acc += sh[warp][i] * s2[i * 64 + j];
        o1 = fmaxf(acc, 0.f);
    }
    float part = o0 * s3[lane] + o1 * s3[lane + 32];
    #pragma unroll
    for (int d2 = 16; d2; d2 >>= 1) part += __shfl_down_sync(0xffffffffu, part, d2);
    if (lane == 0) out[g] = part + __ldg(fb3);
}

// ---------------- launch ----------------
extern "C" void kernel_launch(void* const* d_in, const int* in_sizes, int n_in,
                              void* d_out, int out_size) {
    const float* x     = (const float*)d_in[0];
    const int*   ei    = (const int*)  d_in[1];
    const int*   batch = (const int*)  d_in[2];
    const float* gx    = (const float*)d_in[3];
    const float* w11 = (const float*)d_in[4],  *b11 = (const float*)d_in[5];
    const float* w12 = (const float*)d_in[6],  *b12 = (const float*)d_in[7];
    const float* w21 = (const float*)d_in[8],  *b21 = (const float*)d_in[9];
    const float* w22 = (const float*)d_in[10], *b22 = (const float*)d_in[11];
    const float* w31 = (const float*)d_in[12], *b31 = (const float*)d_in[13];
    const float* w32 = (const float*)d_in[14], *b32 = (const float*)d_in[15];
    const float* g1  = (const float*)d_in[16], *be1 = (const float*)d_in[17];
    const float* g2  = (const float*)d_in[18], *be2 = (const float*)d_in[19];
    const float* g3  = (const float*)d_in[20], *be3 = (const float*)d_in[21];
    const float* fw1 = (const float*)d_in[22], *fb1 = (const float*)d_in[23];
    const float* fw2 = (const float*)d_in[24], *fb2 = (const float*)d_in[25];
    const float* fw3 = (const float*)d_in[26], *fb3 = (const float*)d_in[27];
    float* out = (float*)d_out;

    const int NB_N = (NN + 255) / 256;
    const int NB_E = (EE + 255) / 256;
    const int NB_G = (NTH + 255) / 256;

    zero_kernel<<<3072, 256>>>();
    pack_kernel<<<NB_N, 256>>>(x);

    // build dst-sorted edge list (counting sort)
    hist_kernel<<<NB_E, 256>>>(ei);
    scan1_kernel<<<NBS, 256>>>();
    scan2_kernel<<<1, 512>>>();
    scan3_kernel<<<NB_N, 256>>>();
    scatter_kernel<<<NB_E, 256>>>(ei);

    // layer 1 (5 -> 5 -> 5)
    gather_kernel<5, 0><<<NB_G, 256>>>();
    node_kernel<5, 5, 5, 0><<<NB_N, 256>>>(w11, b11, w12, b12, batch);
    finalize_kernel<<<1, 32>>>(g1, be1, 0, 5);

    // layer 2 (5 -> 10 -> 10), BN(l1) folded
    gather_kernel<5, 1><<<NB_G, 256>>>();
    node_kernel<5, 10, 10, 1><<<NB_N, 256>>>(w21, b21, w22, b22, batch);
    finalize_kernel<<<1, 32>>>(g2, be2, 1, 10);

    // layer 3 (10 -> 10 -> 10), BN(l2) folded, pool fused
    gather_kernel<10, 2><<<NB_G, 256>>>();
    node_kernel<10, 10, 10, 2><<<NB_N, 256>>>(w31, b31, w32, b32, batch);
    finalize_kernel<<<1, 32>>>(g3, be3, 2, 10);

    // final MLP (BN(l3) applied at pooled level)
    fc_kernel<<<GG / 8, 256>>>(gx, fw1, fb1, fw2, fb2, fw3, fb3, out);
}

// round 3
// speedup vs baseline: 1.2424x; 1.1477x over previous
#include <cuda_runtime.h>

#define NN 500000
#define EE 8000000
#define GG 8192
#define BN_EPS 1e-5f
#define NBS 489          // ceil(NN/1024) scan blocks

// ---------------- scratch (device globals; no allocations) ----------------
__device__ __align__(16) float d_h5a[(size_t)NN * 8];
__device__ __align__(16) float d_h5b[(size_t)NN * 8];
__device__ __align__(16) float d_h10[(size_t)NN * 12];
__device__ __align__(16) int   d_esrc[EE];          // src ids, dst-sorted
__device__ int   d_hist[NN];
__device__ int   d_rowptr[NN + 1];
__device__ int   d_pos[NN];
__device__ int   d_bsum[512];
__device__ int   d_bsumx[512];
__device__ float d_stats[3 * 32];   // per layer: sum[0..16), sumsq[16..32)
__device__ float d_aff  [3 * 32];   // per layer: a[0..16), c[16..32)
__device__ float d_psum[GG * 10];
__device__ float d_cnt [GG];

// ---------------- zero scratch (small now: hist + pool accumulators) -------
__global__ void zero_kernel() {
    size_t i = (size_t)blockIdx.x * blockDim.x + threadIdx.x;
    size_t stride = (size_t)gridDim.x * blockDim.x;
    for (size_t k = i; k < NN; k += stride) d_hist[k] = 0;
    for (size_t k = i; k < (size_t)GG * 10; k += stride) d_psum[k] = 0.f;
    for (size_t k = i; k < GG; k += stride) d_cnt[k] = 0.f;
    if (i < 3 * 32) d_stats[i] = 0.f;
}

// ---------------- pack x (N x 5) into 32B rows ----------------
__global__ void pack_kernel(const float* __restrict__ x) {
    int n = blockIdx.x * blockDim.x + threadIdx.x;
    if (n >= NN) return;
    #pragma unroll
    for (int f = 0; f < 5; f++) d_h5a[(size_t)n * 8 + f] = x[(size_t)n * 5 + f];
}

// ---------------- counting sort: histogram over dst ----------------
__global__ __launch_bounds__(256) void hist_kernel(const int* __restrict__ ei) {
    int e = blockIdx.x * blockDim.x + threadIdx.x;
    if (e < EE) atomicAdd(&d_hist[__ldg(ei + EE + e)], 1);
}

// ---------------- scan stage 1: per-block exclusive scan (1024 elems/block) --
__global__ __launch_bounds__(256) void scan1_kernel() {
    __shared__ int wsum[8];
    int tid = threadIdx.x, b = blockIdx.x;
    int lane = tid & 31, warp = tid >> 5;
    int base = b * 1024 + tid * 4;
    int v[4];
    #pragma unroll
    for (int j = 0; j < 4; j++) {
        int idx = base + j;
        v[j] = (idx < NN) ? d_hist[idx] : 0;
    }
    int tsum = v[0] + v[1] + v[2] + v[3];
    int inc = tsum;
    #pragma unroll
    for (int d = 1; d < 32; d <<= 1) {
        int t = __shfl_up_sync(0xffffffffu, inc, d);
        if (lane >= d) inc += t;
    }
    if (lane == 31) wsum[warp] = inc;
    __syncthreads();
    int woff = 0;
    for (int w = 0; w < warp; w++) woff += wsum[w];
    int run = woff + inc - tsum;   // exclusive prefix of this thread
    #pragma unroll
    for (int j = 0; j < 4; j++) {
        int idx = base + j;
        if (idx < NN) d_rowptr[idx] = run;
        run += v[j];
    }
    if (tid == 255) d_bsum[b] = woff + inc;
}

// ---------------- scan stage 2: scan the 489 block sums ----------------
__global__ void scan2_kernel() {
    __shared__ int s[512];
    int tid = threadIdx.x;
    int v = (tid < NBS) ? d_bsum[tid] : 0;
    s[tid] = v;
    __syncthreads();
    for (int d = 1; d < 512; d <<= 1) {
        int t = (tid >= d) ? s[tid - d] : 0;
        __syncthreads();
        s[tid] += t;
        __syncthreads();
    }
    if (tid < NBS) d_bsumx[tid] = s[tid] - v;
}

// ---------------- scan stage 3: add offsets, init pos, cap rowptr ----------
__global__ __launch_bounds__(256) void scan3_kernel() {
    int i = blockIdx.x * 256 + threadIdx.x;
    if (i < NN) {
        int r = d_rowptr[i] + d_bsumx[i >> 10];
        d_rowptr[i] = r;
        d_pos[i] = r;
    }
    if (i == 0) d_rowptr[NN] = EE;
}

// ---------------- scatter: src ids into dst-sorted order ----------------
__global__ __launch_bounds__(256) void scatter_kernel(const int* __restrict__ ei) {
    int e = blockIdx.x * blockDim.x + threadIdx.x;
    if (e >= EE) return;
    int s = __ldg(ei + e);
    int d = __ldg(ei + EE + e);
    int slot = atomicAdd(&d_pos[d], 1);
    d_esrc[slot] = s;
}

// ---------------- fused CSR gather + GIN MLP + BN stats (+ pool on last) ----
// LAYER 0: in d_h5a (str 8) -> out d_h5b ; 1: d_h5b -> d_h10 ; 2: d_h10 -> pool
template<int FIN, int FMID, int FOUT, int LAYER>
__global__ __launch_bounds__(256) void layer_kernel(
    const float* __restrict__ w1, const float* __restrict__ b1,
    const float* __restrict__ w2, const float* __restrict__ b2,
    const int* __restrict__ batch)
{
    constexpr bool AFF  = (LAYER > 0);
    constexpr bool LAST = (LAYER == 2);
    constexpr int HSTR = (FIN == 5) ? 8 : 12;
    __shared__ float sw1[FIN * FMID], sb1[FMID], sw2[FMID * FOUT], sb2[FOUT];
    __shared__ float saff[32];
    __shared__ float redsh[8][2 * FOUT];
    int tid = threadIdx.x;
    if (tid < FIN * FMID)  sw1[tid] = w1[tid];
    if (tid < FMID)        sb1[tid] = b1[tid];
    if (tid < FMID * FOUT) sw2[tid] = w2[tid];
    if (tid < FOUT)        sb2[tid] = b2[tid];
    if (AFF && tid < 32)   saff[tid] = d_aff[(LAYER - 1) * 32 + tid];
    __syncthreads();

    int n = blockIdx.x * 256 + tid;
    bool valid = n < NN;
    float r[FOUT];
    #pragma unroll
    for (int j = 0; j < FOUT; j++) r[j] = 0.f;

    if (valid) {
        const float* hin = (LAYER == 0) ? d_h5a : (LAYER == 1) ? d_h5b : d_h10;
        const float* hp = hin + (size_t)n * HSTR;
        int r0 = __ldg(d_rowptr + n);
        int r1 = __ldg(d_rowptr + n + 1);

        // acc starts with the self term (GIN eps=0: x_i + sum x_j)
        float acc[FIN];
        {
            float4 a = __ldg(reinterpret_cast<const float4*>(hp));
            acc[0] = a.x; acc[1] = a.y; acc[2] = a.z; acc[3] = a.w;
            if (FIN == 5) acc[4] = __ldg(hp + 4);
            else {
                float4 b4 = __ldg(reinterpret_cast<const float4*>(hp) + 1);
                float2 c2 = __ldg(reinterpret_cast<const float2*>(hp + 8));
                acc[4] = b4.x; acc[5] = b4.y; acc[6] = b4.z; acc[7] = b4.w;
                acc[8] = c2.x; acc[9] = c2.y;
            }
        }

        // CSR neighbor gather, 4-way unrolled for MLP
        int e = r0;
        for (; e + 4 <= r1; e += 4) {
            int s0 = __ldg(d_esrc + e);
            int s1 = __ldg(d_esrc + e + 1);
            int s2 = __ldg(d_esrc + e + 2);
            int s3 = __ldg(d_esrc + e + 3);
            const float* p0 = hin + (size_t)s0 * HSTR;
            const float* p1 = hin + (size_t)s1 * HSTR;
            const float* p2 = hin + (size_t)s2 * HSTR;
            const float* p3 = hin + (size_t)s3 * HSTR;
            float4 a0 = __ldg((const float4*)p0);
            float4 a1 = __ldg((const float4*)p1);
            float4 a2 = __ldg((const float4*)p2);
            float4 a3 = __ldg((const float4*)p3);
            if (FIN == 5) {
                float e0 = __ldg(p0 + 4), e1 = __ldg(p1 + 4);
                float e2 = __ldg(p2 + 4), e3 = __ldg(p3 + 4);
                acc[0] += a0.x + a1.x + a2.x + a3.x;
                acc[1] += a0.y + a1.y + a2.y + a3.y;
                acc[2] += a0.z + a1.z + a2.z + a3.z;
                acc[3] += a0.w + a1.w + a2.w + a3.w;
                acc[4] += e0 + e1 + e2 + e3;
            } else {
                float4 b0 = __ldg((const float4*)p0 + 1);
                float4 b1 = __ldg((const float4*)p1 + 1);
                float4 b2 = __ldg((const float4*)p2 + 1);
                float4 b3 = __ldg((const float4*)p3 + 1);
                float2 c0 = __ldg((const float2*)(p0 + 8));
                float2 c1 = __ldg((const float2*)(p1 + 8));
                float2 c2 = __ldg((const float2*)(p2 + 8));
                float2 c3 = __ldg((const float2*)(p3 + 8));
                acc[0] += a0.x + a1.x + a2.x + a3.x;
                acc[1] += a0.y + a1.y + a2.y + a3.y;
                acc[2] += a0.z + a1.z + a2.z + a3.z;
                acc[3] += a0.w + a1.w + a2.w + a3.w;
                acc[4] += b0.x + b1.x + b2.x + b3.x;
                acc[5] += b0.y + b1.y + b2.y + b3.y;
                acc[6] += b0.z + b1.z + b2.z + b3.z;
                acc[7] += b0.w + b1.w + b2.w + b3.w;
                acc[8] += c0.x + c1.x + c2.x + c3.x;
                acc[9] += c0.y + c1.y + c2.y + c3.y;
            }
        }
        for (; e < r1; e++) {
            int s = __ldg(d_esrc + e);
            const float* p = hin + (size_t)s * HSTR;
            float4 a = __ldg((const float4*)p);
            acc[0] += a.x; acc[1] += a.y; acc[2] += a.z; acc[3] += a.w;
            if (FIN == 5) acc[4] += __ldg(p + 4);
            else {
                float4 b4 = __ldg((const float4*)p + 1);
                float2 c2 = __ldg((const float2*)(p + 8));
                acc[4] += b4.x; acc[5] += b4.y; acc[6] += b4.z; acc[7] += b4.w;
                acc[8] += c2.x; acc[9] += c2.y;
            }
        }

        // fold previous layer's BN affine: a*acc + c*(1+deg)
        float t[FIN];
        if (AFF) {
            float degc = 1.0f + (float)(r1 - r0);
            #pragma unroll
            for (int f = 0; f < FIN; f++) t[f] = saff[f] * acc[f] + saff[16 + f] * degc;
        } else {
            #pragma unroll
            for (int f = 0; f < FIN; f++) t[f] = acc[f];
        }

        float u[FMID];
        #pragma unroll
        for (int j = 0; j < FMID; j++) {
            float a = sb1[j];
            #pragma unroll
            for (int i = 0; i < FIN; i++) a += t[i] * sw1[i * FMID + j];
            u[j] = fmaxf(a, 0.f);
        }
        #pragma unroll
        for (int j = 0; j < FOUT; j++) {
            float a = sb2[j];
            #pragma unroll
            for (int i = 0; i < FMID; i++) a += u[i] * sw2[i * FOUT + j];
            r[j] = fmaxf(a, 0.f);
        }
        if (!LAST) {
            float* ho = (LAYER == 0) ? &d_h5b[(size_t)n * 8] : &d_h10[(size_t)n * 12];
            #pragma unroll
            for (int j = 0; j < FOUT; j++) ho[j] = r[j];
        }
    }

    // BN statistics: warp reduce -> shared -> few global atomics per block
    int lane = tid & 31, warp = tid >> 5;
    #pragma unroll
    for (int f = 0; f < FOUT; f++) {
        float s = r[f], q = r[f] * r[f];
        #pragma unroll
        for (int d2 = 16; d2; d2 >>= 1) {
            s += __shfl_down_sync(0xffffffffu, s, d2);
            q += __shfl_down_sync(0xffffffffu, q, d2);
        }
        if (lane == 0) { redsh[warp][f] = s; redsh[warp][FOUT + f] = q; }
    }
    __syncthreads();
    if (tid < 2 * FOUT) {
        float acc2 = 0.f;
        #pragma unroll
        for (int w = 0; w < 8; w++) acc2 += redsh[w][tid];
        float* st = d_stats + LAYER * 32;
        int idx = (tid < FOUT) ? tid : (16 + tid - FOUT);
        atomicAdd(&st[idx], acc2);
    }

    // fused pooling on the last layer (batch sorted; NN % 32 == 0)
    if (LAST && valid) {
        int b = __ldg(batch + n);
        float v[11];
        #pragma unroll
        for (int f = 0; f < 10; f++) v[f] = r[f];
        v[10] = 1.f;
        unsigned m = 0xffffffffu;
        #pragma unroll
        for (int d2 = 1; d2 < 32; d2 <<= 1) {
            int nb = __shfl_down_sync(m, b, d2);
            float nv[11];
            #pragma unroll
            for (int f = 0; f < 11; f++) nv[f] = __shfl_down_sync(m, v[f], d2);
            if (lane + d2 < 32 && nb == b) {
                #pragma unroll
                for (int f = 0; f < 11; f++) v[f] += nv[f];
            }
        }
        int pb = __shfl_up_sync(m, b, 1);
        if (lane == 0 || pb != b) {
            #pragma unroll
            for (int f = 0; f < 10; f++) atomicAdd(&d_psum[(size_t)b * 10 + f], v[f]);
            atomicAdd(&d_cnt[b], v[10]);
        }
    }
}

// ---------------- per-layer BN parameters -> affine (a, c) ----------------
__global__ void finalize_kernel(const float* __restrict__ g, const float* __restrict__ be,
                                int layer, int F) {
    int f = threadIdx.x;
    if (f < F) {
        const float* st = d_stats + layer * 32;
        float mu  = st[f] * (1.0f / NN);
        float var = st[16 + f] * (1.0f / NN) - mu * mu;
        float a = g[f] * rsqrtf(var + BN_EPS);
        d_aff[layer * 32 + f]      = a;
        d_aff[layer * 32 + 16 + f] = be[f] - mu * a;
    }
}

// ---------------- final MLP: one warp per graph ----------------
__global__ __launch_bounds__(256) void fc_kernel(
    const float* __restrict__ gx,
    const float* __restrict__ fw1, const float* __restrict__ fb1,
    const float* __restrict__ fw2, const float* __restrict__ fb2,
    const float* __restrict__ fw3, const float* __restrict__ fb3,
    float* __restrict__ out)
{
    __shared__ float s1[20 * 128];
    __shared__ float s2[128 * 64];
    __shared__ float s3[64];
    __shared__ float sb1[128];
    __shared__ float sb2[64];
    __shared__ float sh[8][128];
    __shared__ float sz[8][20];
    int tid = threadIdx.x;
    for (int k = tid; k < 2560; k += 256) s1[k] = fw1[k];
    for (int k = tid; k < 8192; k += 256) s2[k] = fw2[k];
    if (tid < 64)  s3[tid]  = fw3[tid];
    if (tid < 128) sb1[tid] = fb1[tid];
    if (tid < 64)  sb2[tid] = fb2[tid];

    int warp = tid >> 5, lane = tid & 31;
    int g = blockIdx.x * 8 + warp;
    if (lane < 10) {
        float c = d_cnt[g];
        const float* aff = d_aff + 2 * 32;
        float p = (c > 0.f) ? aff[lane] * (d_psum[(size_t)g * 10 + lane] / c) + aff[16 + lane] : 0.f;
        sz[warp][lane] = p;
        sz[warp][10 + lane] = gx[(size_t)g * 10 + lane];
    }
    __syncthreads();

    float h[4];
    #pragma unroll
    for (int k = 0; k < 4; k++) {
        int j = lane + 32 * k;
        float acc = sb1[j];
        #pragma unroll
        for (int i = 0; i < 20; i++) acc += sz[warp][i] * s1[i * 128 + j];
        h[k] = fmaxf(acc, 0.f);
        sh[warp][j] = h[k];
    }
    __syncwarp();
    float o0, o1;
    {
        int j = lane;
        float acc = sb2[j];
        #pragma unroll 8
        for (int i = 0; i < 128; i++) acc += sh[warp][i] * s2[i * 64 + j];
        o0 = fmaxf(acc, 0.f);
        j = lane + 32;
        acc = sb2[j];
        #pragma unroll 8
        for (int i = 0; i < 128; i++) acc += sh[warp][i] * s2[i * 64 + j];
        o1 = fmaxf(acc, 0.f);
    }
    float part = o0 * s3[lane] + o1 * s3[lane + 32];
    #pragma unroll
    for (int d2 = 16; d2; d2 >>= 1) part += __shfl_down_sync(0xffffffffu, part, d2);
    if (lane == 0) out[g] = part + __ldg(fb3);
}

// ---------------- launch ----------------
extern "C" void kernel_launch(void* const* d_in, const int* in_sizes, int n_in,
                              void* d_out, int out_size) {
    const float* x     = (const float*)d_in[0];
    const int*   ei    = (const int*)  d_in[1];
    const int*   batch = (const int*)  d_in[2];
    const float* gx    = (const float*)d_in[3];
    const float* w11 = (const float*)d_in[4],  *b11 = (const float*)d_in[5];
    const float* w12 = (const float*)d_in[6],  *b12 = (const float*)d_in[7];
    const float* w21 = (const float*)d_in[8],  *b21 = (const float*)d_in[9];
    const float* w22 = (const float*)d_in[10], *b22 = (const float*)d_in[11];
    const float* w31 = (const float*)d_in[12], *b31 = (const float*)d_in[13];
    const float* w32 = (const float*)d_in[14], *b32 = (const float*)d_in[15];
    const float* g1  = (const float*)d_in[16], *be1 = (const float*)d_in[17];
    const float* g2  = (const float*)d_in[18], *be2 = (const float*)d_in[19];
    const float* g3  = (const float*)d_in[20], *be3 = (const float*)d_in[21];
    const float* fw1 = (const float*)d_in[22], *fb1 = (const float*)d_in[23];
    const float* fw2 = (const float*)d_in[24], *fb2 = (const float*)d_in[25];
    const float* fw3 = (const float*)d_in[26], *fb3 = (const float*)d_in[27];
    float* out = (float*)d_out;

    const int NB_N = (NN + 255) / 256;
    const int NB_E = (EE + 255) / 256;

    zero_kernel<<<1024, 256>>>();
    pack_kernel<<<NB_N, 256>>>(x);

    // build dst-sorted src list (counting sort over dst)
    hist_kernel<<<NB_E, 256>>>(ei);
    scan1_kernel<<<NBS, 256>>>();
    scan2_kernel<<<1, 512>>>();
    scan3_kernel<<<NB_N, 256>>>();
    scatter_kernel<<<NB_E, 256>>>(ei);

    // fused CSR-gather + GIN layers
    layer_kernel<5, 5, 5, 0><<<NB_N, 256>>>(w11, b11, w12, b12, batch);
    finalize_kernel<<<1, 32>>>(g1, be1, 0, 5);
    layer_kernel<5, 10, 10, 1><<<NB_N, 256>>>(w21, b21, w22, b22, batch);
    finalize_kernel<<<1, 32>>>(g2, be2, 1, 10);
    layer_kernel<10, 10, 10, 2><<<NB_N, 256>>>(w31, b31, w32, b32, batch);
    finalize_kernel<<<1, 32>>>(g3, be3, 2, 10);

    // final MLP (BN(l3) applied at pooled level)
    fc_kernel<<<GG / 8, 256>>>(gx, fw1, fb1, fw2, fb2, fw3, fb3, out);
}

// round 4
// speedup vs baseline: 1.3655x; 1.0991x over previous
#include <cuda_runtime.h>
#include <cuda_fp16.h>

#define NN 500000
#define EE 8000000
#define GG 8192
#define BN_EPS 1e-5f
#define NBS 489          // ceil(NN/1024) scan blocks

// ---------------- scratch (device globals; no allocations) ----------------
__device__ __align__(16) float  d_h5a[(size_t)NN * 8];   // fp32, 32B rows (5 used)
__device__ __align__(16) float  d_h5b[(size_t)NN * 8];   // fp32, 32B rows (5 used)
__device__ __align__(16) __half d_h10h[(size_t)NN * 16]; // fp16, 32B rows (10 used)
__device__ __align__(16) int    d_esrc[EE];              // src ids, dst-sorted
__device__ int   d_hist[NN];
__device__ int   d_rowptr[NN + 1];
__device__ int   d_pos[NN];
__device__ int   d_bsum[512];
__device__ int   d_bsumx[512];
__device__ float d_stats[3 * 32];   // per layer: sum[0..16), sumsq[16..32)
__device__ float d_aff  [3 * 32];   // per layer: a[0..16), c[16..32)
__device__ float d_psum[GG * 10];
__device__ float d_cnt [GG];

// ---------------- helpers ----------------
__device__ __forceinline__ void cvt8(uint4 u, float* f) {
    float2 t;
    t = __half22float2(*(__half2*)&u.x); f[0] = t.x; f[1] = t.y;
    t = __half22float2(*(__half2*)&u.y); f[2] = t.x; f[3] = t.y;
    t = __half22float2(*(__half2*)&u.z); f[4] = t.x; f[5] = t.y;
    t = __half22float2(*(__half2*)&u.w); f[6] = t.x; f[7] = t.y;
}

// ---------------- zero scratch ----------------
__global__ void zero_kernel() {
    size_t i = (size_t)blockIdx.x * blockDim.x + threadIdx.x;
    size_t stride = (size_t)gridDim.x * blockDim.x;
    for (size_t k = i; k < NN; k += stride) d_hist[k] = 0;
    for (size_t k = i; k < (size_t)GG * 10; k += stride) d_psum[k] = 0.f;
    for (size_t k = i; k < GG; k += stride) d_cnt[k] = 0.f;
    if (i < 3 * 32) d_stats[i] = 0.f;
}

// ---------------- pack x (N x 5) into 32B rows ----------------
__global__ void pack_kernel(const float* __restrict__ x) {
    int n = blockIdx.x * blockDim.x + threadIdx.x;
    if (n >= NN) return;
    float4 a = make_float4(x[(size_t)n * 5], x[(size_t)n * 5 + 1],
                           x[(size_t)n * 5 + 2], x[(size_t)n * 5 + 3]);
    float4 b = make_float4(x[(size_t)n * 5 + 4], 0.f, 0.f, 0.f);
    *(float4*)(d_h5a + (size_t)n * 8)     = a;
    *(float4*)(d_h5a + (size_t)n * 8 + 4) = b;
}

// ---------------- counting sort: histogram over dst ----------------
__global__ __launch_bounds__(256) void hist_kernel(const int* __restrict__ ei) {
    int e = blockIdx.x * blockDim.x + threadIdx.x;
    if (e < EE) atomicAdd(&d_hist[__ldg(ei + EE + e)], 1);
}

// ---------------- scan stage 1 ----------------
__global__ __launch_bounds__(256) void scan1_kernel() {
    __shared__ int wsum[8];
    int tid = threadIdx.x, b = blockIdx.x;
    int lane = tid & 31, warp = tid >> 5;
    int base = b * 1024 + tid * 4;
    int v[4];
    #pragma unroll
    for (int j = 0; j < 4; j++) {
        int idx = base + j;
        v[j] = (idx < NN) ? d_hist[idx] : 0;
    }
    int tsum = v[0] + v[1] + v[2] + v[3];
    int inc = tsum;
    #pragma unroll
    for (int d = 1; d < 32; d <<= 1) {
        int t = __shfl_up_sync(0xffffffffu, inc, d);
        if (lane >= d) inc += t;
    }
    if (lane == 31) wsum[warp] = inc;
    __syncthreads();
    int woff = 0;
    for (int w = 0; w < warp; w++) woff += wsum[w];
    int run = woff + inc - tsum;
    #pragma unroll
    for (int j = 0; j < 4; j++) {
        int idx = base + j;
        if (idx < NN) d_rowptr[idx] = run;
        run += v[j];
    }
    if (tid == 255) d_bsum[b] = woff + inc;
}

// ---------------- scan stage 2 ----------------
__global__ void scan2_kernel() {
    __shared__ int s[512];
    int tid = threadIdx.x;
    int v = (tid < NBS) ? d_bsum[tid] : 0;
    s[tid] = v;
    __syncthreads();
    for (int d = 1; d < 512; d <<= 1) {
        int t = (tid >= d) ? s[tid - d] : 0;
        __syncthreads();
        s[tid] += t;
        __syncthreads();
    }
    if (tid < NBS) d_bsumx[tid] = s[tid] - v;
}

// ---------------- scan stage 3 ----------------
__global__ __launch_bounds__(256) void scan3_kernel() {
    int i = blockIdx.x * 256 + threadIdx.x;
    if (i < NN) {
        int r = d_rowptr[i] + d_bsumx[i >> 10];
        d_rowptr[i] = r;
        d_pos[i] = r;
    }
    if (i == 0) d_rowptr[NN] = EE;
}

// ---------------- scatter: src ids into dst-sorted order ----------------
__global__ __launch_bounds__(256) void scatter_kernel(const int* __restrict__ ei) {
    int e = blockIdx.x * blockDim.x + threadIdx.x;
    if (e >= EE) return;
    int s = __ldg(ei + e);
    int d = __ldg(ei + EE + e);
    int slot = atomicAdd(&d_pos[d], 1);
    d_esrc[slot] = s;
}

// ---------------- fused pair-lane CSR gather + GIN MLP + BN stats (+pool) ----
// LAYER 0: d_h5a(f32) -> d_h5b(f32); 1: d_h5b(f32) -> d_h10h(f16); 2: d_h10h -> pool
template<int FIN, int FMID, int FOUT, int LAYER>
__global__ __launch_bounds__(256) void layer_kernel(
    const float* __restrict__ w1, const float* __restrict__ b1,
    const float* __restrict__ w2, const float* __restrict__ b2,
    const int* __restrict__ batch)
{
    constexpr bool AFF  = (LAYER > 0);
    constexpr bool LAST = (LAYER == 2);
    __shared__ float sw1[FIN * FMID], sb1[FMID], sw2[FMID * FOUT], sb2[FOUT];
    __shared__ float saff[32];
    __shared__ float redsh[8][2 * FOUT];
    int tid = threadIdx.x;
    if (tid < FIN * FMID)  sw1[tid] = w1[tid];
    if (tid < FMID)        sb1[tid] = b1[tid];
    if (tid < FMID * FOUT) sw2[tid] = w2[tid];
    if (tid < FOUT)        sb2[tid] = b2[tid];
    if (AFF && tid < 32)   saff[tid] = d_aff[(LAYER - 1) * 32 + tid];
    __syncthreads();

    int lane = tid & 31, warp = tid >> 5;
    int half = lane & 1;
    int node = (blockIdx.x * 256 + tid) >> 1;   // pair of lanes per node
    bool valid = node < NN;                      // warp-uniform (NN % 16 == 0)
    bool even = (half == 0);
    const unsigned m = 0xffffffffu;

    float r[FOUT];
    #pragma unroll
    for (int j = 0; j < FOUT; j++) r[j] = 0.f;

    if (valid) {
        int r0 = __ldg(d_rowptr + node);
        int r1 = __ldg(d_rowptr + node + 1);
        float t[FIN];

        if (FIN == 5) {
            const float4* base = (const float4*)((LAYER == 0) ? d_h5a : d_h5b);
            float4 acc = __ldg(base + (size_t)node * 2 + half);   // self term
            int e = r0;
            for (; e + 2 <= r1; e += 2) {
                int s0 = __ldg(d_esrc + e);
                int s1 = __ldg(d_esrc + e + 1);
                float4 v0 = __ldg(base + (size_t)s0 * 2 + half);
                float4 v1 = __ldg(base + (size_t)s1 * 2 + half);
                acc.x += v0.x + v1.x; acc.y += v0.y + v1.y;
                acc.z += v0.z + v1.z; acc.w += v0.w + v1.w;
            }
            if (e < r1) {
                int s = __ldg(d_esrc + e);
                float4 v = __ldg(base + (size_t)s * 2 + half);
                acc.x += v.x; acc.y += v.y; acc.z += v.z; acc.w += v.w;
            }
            float f4 = __shfl_xor_sync(m, acc.x, 1);   // even gets odd's feat4-sum
            t[0] = acc.x; t[1] = acc.y; t[2] = acc.z; t[3] = acc.w; t[4] = f4;
        } else {
            const uint4* base = (const uint4*)d_h10h;
            float a[8];
            {
                uint4 u = __ldg(base + (size_t)node * 2 + half);
                cvt8(u, a);
            }
            int e = r0;
            for (; e + 2 <= r1; e += 2) {
                int s0 = __ldg(d_esrc + e);
                int s1 = __ldg(d_esrc + e + 1);
                uint4 u0 = __ldg(base + (size_t)s0 * 2 + half);
                uint4 u1 = __ldg(base + (size_t)s1 * 2 + half);
                float f0[8], f1[8];
                cvt8(u0, f0); cvt8(u1, f1);
                #pragma unroll
                for (int k = 0; k < 8; k++) a[k] += f0[k] + f1[k];
            }
            if (e < r1) {
                int s = __ldg(d_esrc + e);
                uint4 u = __ldg(base + (size_t)s * 2 + half);
                float f0[8];
                cvt8(u, f0);
                #pragma unroll
                for (int k = 0; k < 8; k++) a[k] += f0[k];
            }
            float f8 = __shfl_xor_sync(m, a[0], 1);    // even gets odd's feat8-sum
            float f9 = __shfl_xor_sync(m, a[1], 1);    // even gets odd's feat9-sum
            #pragma unroll
            for (int k = 0; k < 8; k++) t[k] = a[k];
            t[8] = f8; t[9] = f9;
        }

        if (even) {
            if (AFF) {
                float degc = 1.0f + (float)(r1 - r0);
                #pragma unroll
                for (int f = 0; f < FIN; f++) t[f] = saff[f] * t[f] + saff[16 + f] * degc;
            }
            float u[FMID];
            #pragma unroll
            for (int j = 0; j < FMID; j++) {
                float a2 = sb1[j];
                #pragma unroll
                for (int i = 0; i < FIN; i++) a2 += t[i] * sw1[i * FMID + j];
                u[j] = fmaxf(a2, 0.f);
            }
            #pragma unroll
            for (int j = 0; j < FOUT; j++) {
                float a2 = sb2[j];
                #pragma unroll
                for (int i = 0; i < FMID; i++) a2 += u[i] * sw2[i * FOUT + j];
                r[j] = fmaxf(a2, 0.f);
            }
            if (LAYER == 0) {
                *(float4*)(d_h5b + (size_t)node * 8) = make_float4(r[0], r[1], r[2], r[3]);
                d_h5b[(size_t)node * 8 + 4] = r[4];
            } else if (LAYER == 1) {
                __half2 p0 = __floats2half2_rn(r[0], r[1]);
                __half2 p1 = __floats2half2_rn(r[2], r[3]);
                __half2 p2 = __floats2half2_rn(r[4], r[5]);
                __half2 p3 = __floats2half2_rn(r[6], r[7]);
                __half2 p4 = __floats2half2_rn(r[8], r[9]);
                uint4 u;
                u.x = *(unsigned*)&p0; u.y = *(unsigned*)&p1;
                u.z = *(unsigned*)&p2; u.w = *(unsigned*)&p3;
                *(uint4*)(d_h10h + (size_t)node * 16) = u;
                *(unsigned*)(d_h10h + (size_t)node * 16 + 8) = *(unsigned*)&p4;
            }
        }
    }

    // BN statistics (r==0 on odd/invalid lanes)
    #pragma unroll
    for (int f = 0; f < FOUT; f++) {
        float s = r[f], q = r[f] * r[f];
        #pragma unroll
        for (int d2 = 16; d2; d2 >>= 1) {
            s += __shfl_down_sync(m, s, d2);
            q += __shfl_down_sync(m, q, d2);
        }
        if (lane == 0) { redsh[warp][f] = s; redsh[warp][FOUT + f] = q; }
    }
    __syncthreads();
    if (tid < 2 * FOUT) {
        float acc2 = 0.f;
        #pragma unroll
        for (int w = 0; w < 8; w++) acc2 += redsh[w][tid];
        float* st = d_stats + LAYER * 32;
        int idx = (tid < FOUT) ? tid : (16 + tid - FOUT);
        atomicAdd(&st[idx], acc2);
    }

    // fused pooling on last layer: segmented scan over even lanes (batch sorted)
    if (LAST && valid) {
        int b;
        float v[11];
        if (even) {
            b = __ldg(batch + node);
            #pragma unroll
            for (int f = 0; f < 10; f++) v[f] = r[f];
            v[10] = 1.f;
        } else {
            b = -1 - lane;   // unique negative: never merges
            #pragma unroll
            for (int f = 0; f < 11; f++) v[f] = 0.f;
        }
        #pragma unroll
        for (int d2 = 2; d2 < 32; d2 <<= 1) {
            int nb = __shfl_down_sync(m, b, d2);
            float nv[11];
            #pragma unroll
            for (int f = 0; f < 11; f++) nv[f] = __shfl_down_sync(m, v[f], d2);
            if (lane + d2 < 32 && nb == b) {
                #pragma unroll
                for (int f = 0; f < 11; f++) v[f] += nv[f];
            }
        }
        int pb = __shfl_up_sync(m, b, 2);
        if (even && (lane == 0 || pb != b)) {
            #pragma unroll
            for (int f = 0; f < 10; f++) atomicAdd(&d_psum[(size_t)b * 10 + f], v[f]);
            atomicAdd(&d_cnt[b], v[10]);
        }
    }
}

// ---------------- per-layer BN parameters -> affine (a, c) ----------------
__global__ void finalize_kernel(const float* __restrict__ g, const float* __restrict__ be,
                                int layer, int F) {
    int f = threadIdx.x;
    if (f < F) {
        const float* st = d_stats + layer * 32;
        float mu  = st[f] * (1.0f / NN);
        float var = st[16 + f] * (1.0f / NN) - mu * mu;
        float a = g[f] * rsqrtf(var + BN_EPS);
        d_aff[layer * 32 + f]      = a;
        d_aff[layer * 32 + 16 + f] = be[f] - mu * a;
    }
}

// ---------------- final MLP: one warp per graph ----------------
__global__ __launch_bounds__(256) void fc_kernel(
    const float* __restrict__ gx,
    const float* __restrict__ fw1, const float* __restrict__ fb1,
    const float* __restrict__ fw2, const float* __restrict__ fb2,
    const float* __restrict__ fw3, const float* __restrict__ fb3,
    float* __restrict__ out)
{
    __shared__ float s1[20 * 128];
    __shared__ float s2[128 * 64];
    __shared__ float s3[64];
    __shared__ float sb1[128];
    __shared__ float sb2[64];
    __shared__ float sh[8][128];
    __shared__ float sz[8][20];
    int tid = threadIdx.x;
    for (int k = tid; k < 2560; k += 256) s1[k] = fw1[k];
    for (int k = tid; k < 8192; k += 256) s2[k] = fw2[k];
    if (tid < 64)  s3[tid]  = fw3[tid];
    if (tid < 128) sb1[tid] = fb1[tid];
    if (tid < 64)  sb2[tid] = fb2[tid];

    int warp = tid >> 5, lane = tid & 31;
    int g = blockIdx.x * 8 + warp;
    if (lane < 10) {
        float c = d_cnt[g];
        const float* aff = d_aff + 2 * 32;
        float p = (c > 0.f) ? aff[lane] * (d_psum[(size_t)g * 10 + lane] / c) + aff[16 + lane] : 0.f;
        sz[warp][lane] = p;
        sz[warp][10 + lane] = gx[(size_t)g * 10 + lane];
    }
    __syncthreads();

    float h[4];
    #pragma unroll
    for (int k = 0; k < 4; k++) {
        int j = lane + 32 * k;
        float acc = sb1[j];
        #pragma unroll
        for (int i = 0; i < 20; i++) acc += sz[warp][i] * s1[i * 128 + j];
        h[k] = fmaxf(acc, 0.f);
        sh[warp][j] = h[k];
    }
    __syncwarp();
    float o0, o1;
    {
        int j = lane;
        float acc = sb2[j];
        #pragma unroll 8
        for (int i = 0; i < 128; i++) acc += sh[warp][i] * s2[i * 64 + j];
        o0 = fmaxf(acc, 0.f);
        j = lane + 32;
        acc = sb2[j];
        #pragma unroll 8
        for (int i = 0; i < 128; i++) acc += sh[warp][i] * s2[i * 64 + j];
        o1 = fmaxf(acc, 0.f);
    }
    float part = o0 * s3[lane] + o1 * s3[lane + 32];
    #pragma unroll
    for (int d2 = 16; d2; d2 >>= 1) part += __shfl_down_sync(0xffffffffu, part, d2);
    if (lane == 0) out[g] = part + __ldg(fb3);
}

// ---------------- launch ----------------
extern "C" void kernel_launch(void* const* d_in, const int* in_sizes, int n_in,
                              void* d_out, int out_size) {
    const float* x     = (const float*)d_in[0];
    const int*   ei    = (const int*)  d_in[1];
    const int*   batch = (const int*)  d_in[2];
    const float* gx    = (const float*)d_in[3];
    const float* w11 = (const float*)d_in[4],  *b11 = (const float*)d_in[5];
    const float* w12 = (const float*)d_in[6],  *b12 = (const float*)d_in[7];
    const float* w21 = (const float*)d_in[8],  *b21 = (const float*)d_in[9];
    const float* w22 = (const float*)d_in[10], *b22 = (const float*)d_in[11];
    const float* w31 = (const float*)d_in[12], *b31 = (const float*)d_in[13];
    const float* w32 = (const float*)d_in[14], *b32 = (const float*)d_in[15];
    const float* g1  = (const float*)d_in[16], *be1 = (const float*)d_in[17];
    const float* g2  = (const float*)d_in[18], *be2 = (const float*)d_in[19];
    const float* g3  = (const float*)d_in[20], *be3 = (const float*)d_in[21];
    const float* fw1 = (const float*)d_in[22], *fb1 = (const float*)d_in[23];
    const float* fw2 = (const float*)d_in[24], *fb2 = (const float*)d_in[25];
    const float* fw3 = (const float*)d_in[26], *fb3 = (const float*)d_in[27];
    float* out = (float*)d_out;

    const int NB_N = (NN + 255) / 256;
    const int NB_E = (EE + 255) / 256;
    const int NB_L = (NN * 2 + 255) / 256;   // pair-lane layer kernels

    zero_kernel<<<1024, 256>>>();
    pack_kernel<<<NB_N, 256>>>(x);

    // build dst-sorted src list (counting sort over dst)
    hist_kernel<<<NB_E, 256>>>(ei);
    scan1_kernel<<<NBS, 256>>>();
    scan2_kernel<<<1, 512>>>();
    scan3_kernel<<<NB_N, 256>>>();
    scatter_kernel<<<NB_E, 256>>>(ei);

    // fused pair-lane CSR-gather + GIN layers
    layer_kernel<5, 5, 5, 0><<<NB_L, 256>>>(w11, b11, w12, b12, batch);
    finalize_kernel<<<1, 32>>>(g1, be1, 0, 5);
    layer_kernel<5, 10, 10, 1><<<NB_L, 256>>>(w21, b21, w22, b22, batch);
    finalize_kernel<<<1, 32>>>(g2, be2, 1, 10);
    layer_kernel<10, 10, 10, 2><<<NB_L, 256>>>(w31, b31, w32, b32, batch);
    finalize_kernel<<<1, 32>>>(g3, be3, 2, 10);

    // final MLP (BN(l3) applied at pooled level)
    fc_kernel<<<GG / 8, 256>>>(gx, fw1, fb1, fw2, fb2, fw3, fb3, out);
}

// round 5
// speedup vs baseline: 1.4358x; 1.0514x over previous
#include <cuda_runtime.h>
#include <cuda_fp16.h>

#define NN 500000
#define EE 8000000
#define GG 8192
#define BN_EPS 1e-5f
#define NBS 489          // ceil(NN/1024) scan blocks

// ---------------- scratch (device globals; no allocations) ----------------
__device__ __align__(16) __half d_xh [(size_t)NN * 8];   // fp16 x, 16B rows (5 used)
__device__ __align__(16) __half d_h1 [(size_t)NN * 8];   // fp16 h1, 16B rows (5 used)
__device__ __align__(16) __half d_h2 [(size_t)NN * 16];  // fp16 h2, 32B rows (10 used)
__device__ __align__(16) int    d_esrc[EE];              // src ids, dst-sorted
__device__ int   d_hist[NN];
__device__ int   d_rowptr[NN + 1];
__device__ int   d_pos[NN];
__device__ int   d_bsum[512];
__device__ int   d_bsumx[512];
__device__ float d_stats[3 * 32];   // per layer: sum[0..16), sumsq[16..32)
__device__ float d_aff  [3 * 32];   // per layer: a[0..16), c[16..32)
__device__ float d_psum[GG * 10];
__device__ float d_cnt [GG];

// ---------------- helpers ----------------
__device__ __forceinline__ void acc8(uint4 u, float* a) {
    float2 t;
    t = __half22float2(*(__half2*)&u.x); a[0] += t.x; a[1] += t.y;
    t = __half22float2(*(__half2*)&u.y); a[2] += t.x; a[3] += t.y;
    t = __half22float2(*(__half2*)&u.z); a[4] += t.x; a[5] += t.y;
    t = __half22float2(*(__half2*)&u.w); a[6] += t.x; a[7] += t.y;
}

// ---------------- zero scratch ----------------
__global__ void zero_kernel() {
    size_t i = (size_t)blockIdx.x * blockDim.x + threadIdx.x;
    size_t stride = (size_t)gridDim.x * blockDim.x;
    for (size_t k = i; k < NN; k += stride) d_hist[k] = 0;
    for (size_t k = i; k < (size_t)GG * 10; k += stride) d_psum[k] = 0.f;
    for (size_t k = i; k < GG; k += stride) d_cnt[k] = 0.f;
    if (i < 3 * 32) d_stats[i] = 0.f;
}

// ---------------- pack x (N x 5 fp32) into fp16 16B rows ----------------
__global__ void pack_kernel(const float* __restrict__ x) {
    int n = blockIdx.x * blockDim.x + threadIdx.x;
    if (n >= NN) return;
    const float* p = x + (size_t)n * 5;
    __half2 p0 = __floats2half2_rn(p[0], p[1]);
    __half2 p1 = __floats2half2_rn(p[2], p[3]);
    __half2 p2 = __floats2half2_rn(p[4], 0.f);
    __half2 pz = __floats2half2_rn(0.f, 0.f);
    uint4 u;
    u.x = *(unsigned*)&p0; u.y = *(unsigned*)&p1;
    u.z = *(unsigned*)&p2; u.w = *(unsigned*)&pz;
    *(uint4*)(d_xh + (size_t)n * 8) = u;
}

// ---------------- counting sort: histogram over dst (4 edges/thread) -------
__global__ __launch_bounds__(256) void hist_kernel(const int* __restrict__ ei) {
    int t = blockIdx.x * blockDim.x + threadIdx.x;
    if (t >= EE / 4) return;
    int4 d = __ldg((const int4*)(ei + EE) + t);
    atomicAdd(&d_hist[d.x], 1);
    atomicAdd(&d_hist[d.y], 1);
    atomicAdd(&d_hist[d.z], 1);
    atomicAdd(&d_hist[d.w], 1);
}

// ---------------- scan stage 1 ----------------
__global__ __launch_bounds__(256) void scan1_kernel() {
    __shared__ int wsum[8];
    int tid = threadIdx.x, b = blockIdx.x;
    int lane = tid & 31, warp = tid >> 5;
    int base = b * 1024 + tid * 4;
    int v[4];
    #pragma unroll
    for (int j = 0; j < 4; j++) {
        int idx = base + j;
        v[j] = (idx < NN) ? d_hist[idx] : 0;
    }
    int tsum = v[0] + v[1] + v[2] + v[3];
    int inc = tsum;
    #pragma unroll
    for (int d = 1; d < 32; d <<= 1) {
        int t = __shfl_up_sync(0xffffffffu, inc, d);
        if (lane >= d) inc += t;
    }
    if (lane == 31) wsum[warp] = inc;
    __syncthreads();
    int woff = 0;
    for (int w = 0; w < warp; w++) woff += wsum[w];
    int run = woff + inc - tsum;
    #pragma unroll
    for (int j = 0; j < 4; j++) {
        int idx = base + j;
        if (idx < NN) d_rowptr[idx] = run;
        run += v[j];
    }
    if (tid == 255) d_bsum[b] = woff + inc;
}

// ---------------- scan stage 2 ----------------
__global__ void scan2_kernel() {
    __shared__ int s[512];
    int tid = threadIdx.x;
    int v = (tid < NBS) ? d_bsum[tid] : 0;
    s[tid] = v;
    __syncthreads();
    for (int d = 1; d < 512; d <<= 1) {
        int t = (tid >= d) ? s[tid - d] : 0;
        __syncthreads();
        s[tid] += t;
        __syncthreads();
    }
    if (tid < NBS) d_bsumx[tid] = s[tid] - v;
}

// ---------------- scan stage 3 ----------------
__global__ __launch_bounds__(256) void scan3_kernel() {
    int i = blockIdx.x * 256 + threadIdx.x;
    if (i < NN) {
        int r = d_rowptr[i] + d_bsumx[i >> 10];
        d_rowptr[i] = r;
        d_pos[i] = r;
    }
    if (i == 0) d_rowptr[NN] = EE;
}

// ---------------- scatter: src ids into dst-sorted order (4 edges/thread) --
__global__ __launch_bounds__(256) void scatter_kernel(const int* __restrict__ ei) {
    int t = blockIdx.x * blockDim.x + threadIdx.x;
    if (t >= EE / 4) return;
    int4 s = __ldg((const int4*)ei + t);
    int4 d = __ldg((const int4*)(ei + EE) + t);
    d_esrc[atomicAdd(&d_pos[d.x], 1)] = s.x;
    d_esrc[atomicAdd(&d_pos[d.y], 1)] = s.y;
    d_esrc[atomicAdd(&d_pos[d.z], 1)] = s.z;
    d_esrc[atomicAdd(&d_pos[d.w], 1)] = s.w;
}

// ---------------- fused pair-lane CSR gather + GIN MLP + BN stats (+pool) ----
// LAYER 0: d_xh(16B) -> d_h1 ; 1: d_h1(16B) -> d_h2 ; 2: d_h2(32B) -> pool
// F=5 layers: edge-split (each lane of the pair owns alternate edges, full row)
// F=10 layer: row-split (pair splits the 32B row, same sector -> 1 wf/edge)
template<int FIN, int FMID, int FOUT, int LAYER>
__global__ __launch_bounds__(256) void layer_kernel(
    const float* __restrict__ w1, const float* __restrict__ b1,
    const float* __restrict__ w2, const float* __restrict__ b2,
    const int* __restrict__ batch)
{
    constexpr bool AFF  = (LAYER > 0);
    constexpr bool LAST = (LAYER == 2);
    __shared__ float sw1[FIN * FMID], sb1[FMID], sw2[FMID * FOUT], sb2[FOUT];
    __shared__ float saff[32];
    __shared__ float redsh[8][2 * FOUT];
    int tid = threadIdx.x;
    if (tid < FIN * FMID)  sw1[tid] = w1[tid];
    if (tid < FMID)        sb1[tid] = b1[tid];
    if (tid < FMID * FOUT) sw2[tid] = w2[tid];
    if (tid < FOUT)        sb2[tid] = b2[tid];
    if (AFF && tid < 32)   saff[tid] = d_aff[(LAYER - 1) * 32 + tid];
    __syncthreads();

    int lane = tid & 31, warp = tid >> 5;
    int half = lane & 1;
    int node = (blockIdx.x * 256 + tid) >> 1;
    bool valid = node < NN;                 // warp-uniform
    bool even = (half == 0);
    const unsigned m = 0xffffffffu;

    float r[FOUT];
    #pragma unroll
    for (int j = 0; j < FOUT; j++) r[j] = 0.f;

    if (valid) {
        int r0 = __ldg(d_rowptr + node);
        int r1 = __ldg(d_rowptr + node + 1);
        float t[FIN];

        if (FIN == 5) {
            // edge-split over fp16 16B rows
            const uint4* base = (const uint4*)((LAYER == 0) ? d_xh : d_h1);
            float a[8];
            #pragma unroll
            for (int k = 0; k < 8; k++) a[k] = 0.f;
            if (even) acc8(__ldg(base + node), a);   // self term
            int e = r0 + half;
            for (; e + 2 < r1; e += 4) {
                int s0 = __ldg(d_esrc + e);
                int s1 = __ldg(d_esrc + e + 2);
                uint4 u0 = __ldg(base + s0);
                uint4 u1 = __ldg(base + s1);
                acc8(u0, a);
                acc8(u1, a);
            }
            if (e < r1) acc8(__ldg(base + __ldg(d_esrc + e)), a);
            // merge the two lanes' partial sums
            #pragma unroll
            for (int k = 0; k < 5; k++) a[k] += __shfl_xor_sync(m, a[k], 1);
            #pragma unroll
            for (int k = 0; k < 5; k++) t[k] = a[k];
        } else {
            // row-split over fp16 32B rows (halves 0-7 | 8-9+pad)
            const uint4* base = (const uint4*)d_h2;
            float a[8];
            #pragma unroll
            for (int k = 0; k < 8; k++) a[k] = 0.f;
            acc8(__ldg(base + (size_t)node * 2 + half), a);   // self half
            int e = r0;
            for (; e + 2 <= r1; e += 2) {
                int s0 = __ldg(d_esrc + e);
                int s1 = __ldg(d_esrc + e + 1);
                uint4 u0 = __ldg(base + (size_t)s0 * 2 + half);
                uint4 u1 = __ldg(base + (size_t)s1 * 2 + half);
                acc8(u0, a);
                acc8(u1, a);
            }
            if (e < r1) acc8(__ldg(base + (size_t)__ldg(d_esrc + e) * 2 + half), a);
            float f8 = __shfl_xor_sync(m, a[0], 1);
            float f9 = __shfl_xor_sync(m, a[1], 1);
            #pragma unroll
            for (int k = 0; k < 8; k++) t[k] = a[k];
            t[8] = f8; t[9] = f9;
        }

        if (even) {
            if (AFF) {
                float degc = 1.0f + (float)(r1 - r0);
                #pragma unroll
                for (int f = 0; f < FIN; f++) t[f] = saff[f] * t[f] + saff[16 + f] * degc;
            }
            float u[FMID];
            #pragma unroll
            for (int j = 0; j < FMID; j++) {
                float a2 = sb1[j];
                #pragma unroll
                for (int i = 0; i < FIN; i++) a2 += t[i] * sw1[i * FMID + j];
                u[j] = fmaxf(a2, 0.f);
            }
            #pragma unroll
            for (int j = 0; j < FOUT; j++) {
                float a2 = sb2[j];
                #pragma unroll
                for (int i = 0; i < FMID; i++) a2 += u[i] * sw2[i * FOUT + j];
                r[j] = fmaxf(a2, 0.f);
            }
            if (LAYER == 0) {
                __half2 p0 = __floats2half2_rn(r[0], r[1]);
                __half2 p1 = __floats2half2_rn(r[2], r[3]);
                __half2 p2 = __floats2half2_rn(r[4], 0.f);
                __half2 pz = __floats2half2_rn(0.f, 0.f);
                uint4 u4;
                u4.x = *(unsigned*)&p0; u4.y = *(unsigned*)&p1;
                u4.z = *(unsigned*)&p2; u4.w = *(unsigned*)&pz;
                *(uint4*)(d_h1 + (size_t)node * 8) = u4;
            } else if (LAYER == 1) {
                __half2 p0 = __floats2half2_rn(r[0], r[1]);
                __half2 p1 = __floats2half2_rn(r[2], r[3]);
                __half2 p2 = __floats2half2_rn(r[4], r[5]);
                __half2 p3 = __floats2half2_rn(r[6], r[7]);
                __half2 p4 = __floats2half2_rn(r[8], r[9]);
                __half2 pz = __floats2half2_rn(0.f, 0.f);
                uint4 u4, u5;
                u4.x = *(unsigned*)&p0; u4.y = *(unsigned*)&p1;
                u4.z = *(unsigned*)&p2; u4.w = *(unsigned*)&p3;
                u5.x = *(unsigned*)&p4; u5.y = *(unsigned*)&pz;
                u5.z = *(unsigned*)&pz; u5.w = *(unsigned*)&pz;
                *(uint4*)(d_h2 + (size_t)node * 16)     = u4;
                *(uint4*)(d_h2 + (size_t)node * 16 + 8) = u5;
            }
        }
    }

    // BN statistics (r==0 on odd/invalid lanes)
    #pragma unroll
    for (int f = 0; f < FOUT; f++) {
        float s = r[f], q = r[f] * r[f];
        #pragma unroll
        for (int d2 = 16; d2; d2 >>= 1) {
            s += __shfl_down_sync(m, s, d2);
            q += __shfl_down_sync(m, q, d2);
        }
        if (lane == 0) { redsh[warp][f] = s; redsh[warp][FOUT + f] = q; }
    }
    __syncthreads();
    if (tid < 2 * FOUT) {
        float acc2 = 0.f;
        #pragma unroll
        for (int w = 0; w < 8; w++) acc2 += redsh[w][tid];
        float* st = d_stats + LAYER * 32;
        int idx = (tid < FOUT) ? tid : (16 + tid - FOUT);
        atomicAdd(&st[idx], acc2);
    }

    // fused pooling on last layer: segmented scan over even lanes (batch sorted)
    if (LAST && valid) {
        int b;
        float v[11];
        if (even) {
            b = __ldg(batch + node);
            #pragma unroll
            for (int f = 0; f < 10; f++) v[f] = r[f];
            v[10] = 1.f;
        } else {
            b = -1 - lane;
            #pragma unroll
            for (int f = 0; f < 11; f++) v[f] = 0.f;
        }
        #pragma unroll
        for (int d2 = 2; d2 < 32; d2 <<= 1) {
            int nb = __shfl_down_sync(m, b, d2);
            float nv[11];
            #pragma unroll
            for (int f = 0; f < 11; f++) nv[f] = __shfl_down_sync(m, v[f], d2);
            if (lane + d2 < 32 && nb == b) {
                #pragma unroll
                for (int f = 0; f < 11; f++) v[f] += nv[f];
            }
        }
        int pb = __shfl_up_sync(m, b, 2);
        if (even && (lane == 0 || pb != b)) {
            #pragma unroll
            for (int f = 0; f < 10; f++) atomicAdd(&d_psum[(size_t)b * 10 + f], v[f]);
            atomicAdd(&d_cnt[b], v[10]);
        }
    }
}

// ---------------- per-layer BN parameters -> affine (a, c) ----------------
__global__ void finalize_kernel(const float* __restrict__ g, const float* __restrict__ be,
                                int layer, int F) {
    int f = threadIdx.x;
    if (f < F) {
        const float* st = d_stats + layer * 32;
        float mu  = st[f] * (1.0f / NN);
        float var = st[16 + f] * (1.0f / NN) - mu * mu;
        float a = g[f] * rsqrtf(var + BN_EPS);
        d_aff[layer * 32 + f]      = a;
        d_aff[layer * 32 + 16 + f] = be[f] - mu * a;
    }
}

// ---------------- final MLP: one warp per graph ----------------
__global__ __launch_bounds__(256) void fc_kernel(
    const float* __restrict__ gx,
    const float* __restrict__ fw1, const float* __restrict__ fb1,
    const float* __restrict__ fw2, const float* __restrict__ fb2,
    const float* __restrict__ fw3, const float* __restrict__ fb3,
    float* __restrict__ out)
{
    __shared__ float s1[20 * 128];
    __shared__ float s2[128 * 64];
    __shared__ float s3[64];
    __shared__ float sb1[128];
    __shared__ float sb2[64];
    __shared__ float sh[8][128];
    __shared__ float sz[8][20];
    int tid = threadIdx.x;
    for (int k = tid; k < 2560; k += 256) s1[k] = fw1[k];
    for (int k = tid; k < 8192; k += 256) s2[k] = fw2[k];
    if (tid < 64)  s3[tid]  = fw3[tid];
    if (tid < 128) sb1[tid] = fb1[tid];
    if (tid < 64)  sb2[tid] = fb2[tid];

    int warp = tid >> 5, lane = tid & 31;
    int g = blockIdx.x * 8 + warp;
    if (lane < 10) {
        float c = d_cnt[g];
        const float* aff = d_aff + 2 * 32;
        float p = (c > 0.f) ? aff[lane] * (d_psum[(size_t)g * 10 + lane] / c) + aff[16 + lane] : 0.f;
        sz[warp][lane] = p;
        sz[warp][10 + lane] = gx[(size_t)g * 10 + lane];
    }
    __syncthreads();

    float h[4];
    #pragma unroll
    for (int k = 0; k < 4; k++) {
        int j = lane + 32 * k;
        float acc = sb1[j];
        #pragma unroll
        for (int i = 0; i < 20; i++) acc += sz[warp][i] * s1[i * 128 + j];
        h[k] = fmaxf(acc, 0.f);
        sh[warp][j] = h[k];
    }
    __syncwarp();
    float o0, o1;
    {
        int j = lane;
        float acc = sb2[j];
        #pragma unroll 8
        for (int i = 0; i < 128; i++) acc += sh[warp][i] * s2[i * 64 + j];
        o0 = fmaxf(acc, 0.f);
        j = lane + 32;
        acc = sb2[j];
        #pragma unroll 8
        for (int i = 0; i < 128; i++) acc += sh[warp][i] * s2[i * 64 + j];
        o1 = fmaxf(acc, 0.f);
    }
    float part = o0 * s3[lane] + o1 * s3[lane + 32];
    #pragma unroll
    for (int d2 = 16; d2; d2 >>= 1) part += __shfl_down_sync(0xffffffffu, part, d2);
    if (lane == 0) out[g] = part + __ldg(fb3);
}

// ---------------- launch ----------------
extern "C" void kernel_launch(void* const* d_in, const int* in_sizes, int n_in,
                              void* d_out, int out_size) {
    const float* x     = (const float*)d_in[0];
    const int*   ei    = (const int*)  d_in[1];
    const int*   batch = (const int*)  d_in[2];
    const float* gx    = (const float*)d_in[3];
    const float* w11 = (const float*)d_in[4],  *b11 = (const float*)d_in[5];
    const float* w12 = (const float*)d_in[6],  *b12 = (const float*)d_in[7];
    const float* w21 = (const float*)d_in[8],  *b21 = (const float*)d_in[9];
    const float* w22 = (const float*)d_in[10], *b22 = (const float*)d_in[11];
    const float* w31 = (const float*)d_in[12], *b31 = (const float*)d_in[13];
    const float* w32 = (const float*)d_in[14], *b32 = (const float*)d_in[15];
    const float* g1  = (const float*)d_in[16], *be1 = (const float*)d_in[17];
    const float* g2  = (const float*)d_in[18], *be2 = (const float*)d_in[19];
    const float* g3  = (const float*)d_in[20], *be3 = (const float*)d_in[21];
    const float* fw1 = (const float*)d_in[22], *fb1 = (const float*)d_in[23];
    const float* fw2 = (const float*)d_in[24], *fb2 = (const float*)d_in[25];
    const float* fw3 = (const float*)d_in[26], *fb3 = (const float*)d_in[27];
    float* out = (float*)d_out;

    const int NB_N  = (NN + 255) / 256;
    const int NB_E4 = (EE / 4 + 255) / 256;
    const int NB_L  = (NN * 2 + 255) / 256;

    zero_kernel<<<1024, 256>>>();
    pack_kernel<<<NB_N, 256>>>(x);

    // build dst-sorted src list (counting sort over dst)
    hist_kernel<<<NB_E4, 256>>>(ei);
    scan1_kernel<<<NBS, 256>>>();
    scan2_kernel<<<1, 512>>>();
    scan3_kernel<<<NB_N, 256>>>();
    scatter_kernel<<<NB_E4, 256>>>(ei);

    // fused pair-lane CSR-gather + GIN layers
    layer_kernel<5, 5, 5, 0><<<NB_L, 256>>>(w11, b11, w12, b12, batch);
    finalize_kernel<<<1, 32>>>(g1, be1, 0, 5);
    layer_kernel<5, 10, 10, 1><<<NB_L, 256>>>(w21, b21, w22, b22, batch);
    finalize_kernel<<<1, 32>>>(g2, be2, 1, 10);
    layer_kernel<10, 10, 10, 2><<<NB_L, 256>>>(w31, b31, w32, b32, batch);
    finalize_kernel<<<1, 32>>>(g3, be3, 2, 10);

    // final MLP (BN(l3) applied at pooled level)
    fc_kernel<<<GG / 8, 256>>>(gx, fw1, fb1, fw2, fb2, fw3, fb3, out);
}